// round 1
// baseline (speedup 1.0000x reference)
#include <cuda_runtime.h>
#include <math.h>

#define HW 4096

// ---------------- scratch (device globals; no allocation allowed) ----------------
__device__ float g_t1[8*64*HW];                       // box conv3x3 + GELU out
__device__ float g_boxes[8*4*HW];                     // box 1x1 + sigmoid out
__device__ float g_e1[8*64*HW];                       // edge conv3x3 out (pre-GN)
__device__ float g_gn_mean[64];
__device__ float g_gn_rstd[64];
__device__ float g_edge[8*8*HW];                      // edge logits (B,NH,H,W)
__device__ __align__(16) float g_qkv[8*1536*HW];      // qkv 1x1 out
__device__ __align__(16) float g_attn[8*8*64*HW];     // attn scores / probs
__device__ __align__(16) float g_agg[8*512*HW];       // attention output (B,C,H,W)
__device__ float g_y[8*512*HW];                       // fusion conv out (pre-BN)
__device__ float g_bn_mean[512];
__device__ float g_bn_rstd[512];

__device__ __forceinline__ float gelu_exact(float v) {
    return 0.5f * v * (1.0f + erff(v * 0.70710678118654752f));
}
__device__ __forceinline__ float sigmoidf_(float v) {
    return 1.0f / (1.0f + expf(-v));
}

// ---------------- K1: conv3x3 512->64 + bias + GELU -> g_t1 ----------------
// block = one (b, y) row; 256 thr = 64 oc x 4 wslots (16 contiguous w each)
__global__ __launch_bounds__(256) void k1_boxconv_gelu(
    const float* __restrict__ x, const float* __restrict__ w,
    const float* __restrict__ bias)
{
    int y = blockIdx.x, b = blockIdx.y;
    __shared__ float xs[32][3][66];
    int tid = threadIdx.x;
    int oc = tid >> 2, ws4 = tid & 3;
    float acc[16];
#pragma unroll
    for (int j = 0; j < 16; j++) acc[j] = 0.f;

    for (int cc = 0; cc < 16; cc++) {
        for (int idx = tid; idx < 32*3*66; idx += 256) {
            int ic = idx / 198; int rem = idx - ic*198;
            int r = rem / 66;   int col = rem - r*66;
            int gy = y + r - 1, gx = col - 1;
            float v = 0.f;
            if ((unsigned)gy < 64u && (unsigned)gx < 64u)
                v = x[((b*512 + cc*32 + ic)*64 + gy)*64 + gx];
            xs[ic][r][col] = v;
        }
        __syncthreads();
        for (int ic = 0; ic < 32; ic++) {
            int icg = cc*32 + ic;
            const float* wp = &w[(oc*512 + icg)*9];
#pragma unroll
            for (int r = 0; r < 3; r++) {
                float xr[18];
#pragma unroll
                for (int t = 0; t < 18; t++) xr[t] = xs[ic][r][ws4*16 + t];
                float w0 = wp[r*3+0], w1 = wp[r*3+1], w2 = wp[r*3+2];
#pragma unroll
                for (int j = 0; j < 16; j++)
                    acc[j] += xr[j]*w0 + xr[j+1]*w1 + xr[j+2]*w2;
            }
        }
        __syncthreads();
    }
    float bv = bias[oc];
#pragma unroll
    for (int j = 0; j < 16; j++)
        g_t1[((b*64 + oc)*64 + y)*64 + ws4*16 + j] = gelu_exact(acc[j] + bv);
}

// ---------------- K2: conv1x1 64->4 + sigmoid -> g_boxes ----------------
__global__ __launch_bounds__(256) void k2_box1x1_sig(
    const float* __restrict__ w, const float* __restrict__ bias)
{
    __shared__ float ws[256];
    int tid = threadIdx.x;
    ws[tid] = w[tid];
    __syncthreads();
    int idx = blockIdx.x*256 + tid;          // 8*4096 pixels
    int b = idx >> 12, p = idx & 4095;
    float a0 = 0.f, a1 = 0.f, a2 = 0.f, a3 = 0.f;
    for (int c = 0; c < 64; c++) {
        float v = g_t1[(b*64 + c)*HW + p];
        a0 += v*ws[c]; a1 += v*ws[64+c]; a2 += v*ws[128+c]; a3 += v*ws[192+c];
    }
    g_boxes[(b*4+0)*HW + p] = sigmoidf_(a0 + bias[0]);
    g_boxes[(b*4+1)*HW + p] = sigmoidf_(a1 + bias[1]);
    g_boxes[(b*4+2)*HW + p] = sigmoidf_(a2 + bias[2]);
    g_boxes[(b*4+3)*HW + p] = sigmoidf_(a3 + bias[3]);
}

// ---------------- K3: conv3x3 4->64 on boxes -> g_e1 ----------------
__global__ __launch_bounds__(256) void k3_edgeconv(
    const float* __restrict__ w, const float* __restrict__ bias)
{
    __shared__ float ws[2304];
    int tid = threadIdx.x;
    for (int i = tid; i < 2304; i += 256) ws[i] = w[i];
    __syncthreads();
    int idx = blockIdx.x*256 + tid;          // 8*64*4096 outputs
    int p = idx & 4095; int t2 = idx >> 12;
    int oc = t2 & 63;  int b = t2 >> 6;
    int y = p >> 6, xx = p & 63;
    float acc = bias[oc];
#pragma unroll
    for (int ic = 0; ic < 4; ic++) {
        const float* bp = &g_boxes[(b*4 + ic)*HW];
#pragma unroll
        for (int ky = 0; ky < 3; ky++) {
            int gy = y + ky - 1;
            if ((unsigned)gy >= 64u) continue;
#pragma unroll
            for (int kx = 0; kx < 3; kx++) {
                int gx = xx + kx - 1;
                if ((unsigned)gx < 64u)
                    acc += bp[gy*64 + gx] * ws[oc*36 + ic*9 + ky*3 + kx];
            }
        }
    }
    g_e1[idx] = acc;
}

// ---------------- K4: GroupNorm stats (per b,group) ----------------
__global__ __launch_bounds__(256) void k4_gnstats()
{
    int bg = blockIdx.x;                         // b*8+g; channels contiguous
    const float* base = &g_e1[bg * (8*HW)];
    float s = 0.f, ss = 0.f;
    for (int i = threadIdx.x; i < 8*HW; i += 256) {
        float v = base[i]; s += v; ss += v*v;
    }
    __shared__ float s1[8], s2[8];
    int tid = threadIdx.x;
#pragma unroll
    for (int o = 16; o; o >>= 1) {
        s  += __shfl_down_sync(0xffffffffu, s,  o);
        ss += __shfl_down_sync(0xffffffffu, ss, o);
    }
    if ((tid & 31) == 0) { s1[tid>>5] = s; s2[tid>>5] = ss; }
    __syncthreads();
    if (tid == 0) {
        float S = 0.f, SS = 0.f;
#pragma unroll
        for (int i = 0; i < 8; i++) { S += s1[i]; SS += s2[i]; }
        float m = S * (1.0f/32768.f);
        float var = SS * (1.0f/32768.f) - m*m;
        g_gn_mean[bg] = m;
        g_gn_rstd[bg] = rsqrtf(var + 1e-5f);
    }
}

// ---------------- K5: GN + GELU + conv1x1 64->8 -> g_edge ----------------
__global__ __launch_bounds__(256) void k5_edge2(
    const float* __restrict__ gn_g, const float* __restrict__ gn_b,
    const float* __restrict__ w2, const float* __restrict__ b2)
{
    __shared__ float ws[512], gg[64], gb[64], gm[8], gr[8];
    int tid = threadIdx.x;
    for (int i = tid; i < 512; i += 256) ws[i] = w2[i];
    if (tid < 64) { gg[tid] = gn_g[tid]; gb[tid] = gn_b[tid]; }
    int idx = blockIdx.x*256 + tid;
    int b = idx >> 12, p = idx & 4095;          // same b across block
    if (tid < 8) { gm[tid] = g_gn_mean[b*8 + tid]; gr[tid] = g_gn_rstd[b*8 + tid]; }
    __syncthreads();
    float acc[8];
#pragma unroll
    for (int o = 0; o < 8; o++) acc[o] = b2[o];
    for (int c = 0; c < 64; c++) {
        float v = g_e1[(b*64 + c)*HW + p];
        int g = c >> 3;
        v = (v - gm[g]) * gr[g] * gg[c] + gb[c];
        v = gelu_exact(v);
#pragma unroll
        for (int o = 0; o < 8; o++) acc[o] += v * ws[o*64 + c];
    }
#pragma unroll
    for (int o = 0; o < 8; o++) g_edge[(b*8 + o)*HW + p] = acc[o];
}

// ---------------- K6: qkv 1x1 conv = GEMM (1536x512)@(512x4096) per b ----------------
__global__ __launch_bounds__(256) void k6_qkv(
    const float* __restrict__ x, const float* __restrict__ w,
    const float* __restrict__ bias)
{
    int pt = blockIdx.x, ot = blockIdx.y, b = blockIdx.z;
    __shared__ __align__(16) float As[16][68];   // [k][oc]
    __shared__ __align__(16) float Bs[16][68];   // [k][px]
    int tid = threadIdx.x;
    int tx = tid & 15, ty = tid >> 4;
    float c[4][4];
#pragma unroll
    for (int i = 0; i < 4; i++)
#pragma unroll
        for (int j = 0; j < 4; j++) c[i][j] = 0.f;

    int aoc = tid >> 2;                // 0..63
    int ak  = (tid & 3) * 4;           // 0,4,8,12
    int bk  = tid >> 4;                // 0..15
    int bp  = (tid & 15) * 4;
    const float* wbase = w + (ot*64 + aoc)*512;

    for (int kc = 0; kc < 32; kc++) {
        float4 av = *(const float4*)(wbase + kc*16 + ak);
        float4 bv = *(const float4*)(x + (size_t)(b*512 + kc*16 + bk)*HW + pt*64 + bp);
        As[ak+0][aoc] = av.x; As[ak+1][aoc] = av.y;
        As[ak+2][aoc] = av.z; As[ak+3][aoc] = av.w;
        *(float4*)&Bs[bk][bp] = bv;
        __syncthreads();
#pragma unroll
        for (int kk = 0; kk < 16; kk++) {
            float4 a4 = *(const float4*)&As[kk][ty*4];
            float4 b4 = *(const float4*)&Bs[kk][tx*4];
            float aa[4] = {a4.x, a4.y, a4.z, a4.w};
            float bb[4] = {b4.x, b4.y, b4.z, b4.w};
#pragma unroll
            for (int i = 0; i < 4; i++)
#pragma unroll
                for (int j = 0; j < 4; j++) c[i][j] += aa[i]*bb[j];
        }
        __syncthreads();
    }
#pragma unroll
    for (int i = 0; i < 4; i++) {
        int oc = ot*64 + ty*4 + i;
        float bvs = bias[oc];
#pragma unroll
        for (int j = 0; j < 4; j++)
            g_qkv[(size_t)(b*1536 + oc)*HW + pt*64 + tx*4 + j] = c[i][j] + bvs;
    }
}

// ---------------- K7a: scores S = scale*Q^T K + edge  (block per b,h,i) ----------------
__global__ __launch_bounds__(256) void k7a_scores()
{
    int bhi = blockIdx.x;
    int i = bhi & 63, bh = bhi >> 6;
    int h = bh & 7,  b  = bh >> 3;
    __shared__ __align__(16) float Qs[64][68];   // [d][w]
    __shared__ __align__(16) float Ks[64][68];   // [d][W']
    int tid = threadIdx.x;
    const float* qpl = &g_qkv[(size_t)(b*1536 +       h*64 + i)*HW];
    const float* kpl = &g_qkv[(size_t)(b*1536 + 512 + h*64 + i)*HW];
    for (int t = tid; t < 1024; t += 256) {
        int d = t >> 4, w4 = (t & 15)*4;
        *(float4*)&Qs[d][w4] = *(const float4*)(qpl + d*64 + w4);
        *(float4*)&Ks[d][w4] = *(const float4*)(kpl + d*64 + w4);
    }
    __syncthreads();
    int tx = tid & 15, ty = tid >> 4;
    float c[4][4];
#pragma unroll
    for (int ii = 0; ii < 4; ii++)
#pragma unroll
        for (int jj = 0; jj < 4; jj++) c[ii][jj] = 0.f;
#pragma unroll 4
    for (int d = 0; d < 64; d++) {
        float4 a4 = *(const float4*)&Qs[d][ty*4];
        float4 b4 = *(const float4*)&Ks[d][tx*4];
        float aa[4] = {a4.x, a4.y, a4.z, a4.w};
        float bb[4] = {b4.x, b4.y, b4.z, b4.w};
#pragma unroll
        for (int ii = 0; ii < 4; ii++)
#pragma unroll
            for (int jj = 0; jj < 4; jj++) c[ii][jj] += aa[ii]*bb[jj];
    }
    float ev[4];
#pragma unroll
    for (int ii = 0; ii < 4; ii++)
        ev[ii] = g_edge[(b*8 + h)*HW + i*64 + ty*4 + ii];
#pragma unroll
    for (int ii = 0; ii < 4; ii++)
#pragma unroll
        for (int jj = 0; jj < 4; jj++)
            g_attn[(size_t)bhi*4096 + (ty*4+ii)*64 + tx*4 + jj] =
                c[ii][jj]*0.125f + ev[ii];
}

// ---------------- K7b: softmax over i axis (stride 4096) ----------------
__global__ __launch_bounds__(64) void k7b_softmax()
{
    int bhw = blockIdx.x;
    int w = bhw & 63, bh = bhw >> 6;
    int Wp = threadIdx.x;
    float* base = &g_attn[(size_t)bh*64*4096 + w*64 + Wp];
    float vals[64];
    float m = -1e30f;
#pragma unroll
    for (int i = 0; i < 64; i++) { vals[i] = base[(size_t)i*4096]; m = fmaxf(m, vals[i]); }
    float s = 0.f;
#pragma unroll
    for (int i = 0; i < 64; i++) { vals[i] = expf(vals[i] - m); s += vals[i]; }
    float r = 1.0f / s;
#pragma unroll
    for (int i = 0; i < 64; i++) base[(size_t)i*4096] = vals[i] * r;
}

// ---------------- K7c: agg(d,w) = sum_W' V(d,W') P(w,W')  (block per b,h,i) ----------------
__global__ __launch_bounds__(256) void k7c_agg()
{
    int bhi = blockIdx.x;
    int i = bhi & 63, bh = bhi >> 6;
    int h = bh & 7,  b  = bh >> 3;
    __shared__ float Vt[64][65];   // [W'][d]
    __shared__ float Pt[64][65];   // [W'][w]
    int tid = threadIdx.x;
    const float* vpl = &g_qkv[(size_t)(b*1536 + 1024 + h*64 + i)*HW];
    const float* ppl = &g_attn[(size_t)bhi*4096];
    for (int t = tid; t < 1024; t += 256) {
        int rr = t >> 4, k4 = (t & 15)*4;
        float4 v4 = *(const float4*)(vpl + rr*64 + k4);
        Vt[k4+0][rr] = v4.x; Vt[k4+1][rr] = v4.y; Vt[k4+2][rr] = v4.z; Vt[k4+3][rr] = v4.w;
        float4 p4 = *(const float4*)(ppl + rr*64 + k4);
        Pt[k4+0][rr] = p4.x; Pt[k4+1][rr] = p4.y; Pt[k4+2][rr] = p4.z; Pt[k4+3][rr] = p4.w;
    }
    __syncthreads();
    int tx = tid & 15, ty = tid >> 4;
    float c[4][4];
#pragma unroll
    for (int ii = 0; ii < 4; ii++)
#pragma unroll
        for (int jj = 0; jj < 4; jj++) c[ii][jj] = 0.f;
#pragma unroll 4
    for (int k = 0; k < 64; k++) {
        float aa[4], bb[4];
#pragma unroll
        for (int u = 0; u < 4; u++) { aa[u] = Vt[k][ty*4+u]; bb[u] = Pt[k][tx*4+u]; }
#pragma unroll
        for (int ii = 0; ii < 4; ii++)
#pragma unroll
            for (int jj = 0; jj < 4; jj++) c[ii][jj] += aa[ii]*bb[jj];
    }
#pragma unroll
    for (int ii = 0; ii < 4; ii++) {
        int d = ty*4 + ii;
#pragma unroll
        for (int jj = 0; jj < 4; jj++)
            g_agg[(size_t)(b*512 + h*64 + i)*HW + d*64 + tx*4 + jj] = c[ii][jj];
    }
}

// ---------------- K8: fusion conv3x3 1024->512 + bias -> g_y ----------------
// block: 64 oc x (2 rows x 64 w) of one b; 256 thr = 64 oc x 4 wslots(16 w)
__global__ __launch_bounds__(256) void k8_fusion(
    const float* __restrict__ x, const float* __restrict__ w,
    const float* __restrict__ bias)
{
    int ot = blockIdx.x, yt = blockIdx.y, b = blockIdx.z;
    int y0 = yt*2;
    __shared__ float xs[32][4][66];
    int tid = threadIdx.x;
    int oc = ot*64 + (tid >> 2);
    int ws4 = tid & 3;
    float acc0[16], acc1[16];
#pragma unroll
    for (int j = 0; j < 16; j++) { acc0[j] = 0.f; acc1[j] = 0.f; }

    for (int cc = 0; cc < 32; cc++) {
        const float* src = (cc < 16) ? x : g_agg;
        int icb = (cc & 15)*32;
        for (int idx = tid; idx < 32*4*66; idx += 256) {
            int ic = idx / 264; int rem = idx - ic*264;
            int r = rem / 66;   int col = rem - r*66;
            int gy = y0 + r - 1, gx = col - 1;
            float v = 0.f;
            if ((unsigned)gy < 64u && (unsigned)gx < 64u)
                v = src[(size_t)(b*512 + icb + ic)*HW + gy*64 + gx];
            xs[ic][r][col] = v;
        }
        __syncthreads();
        int icgBase = cc*32;
        for (int ic = 0; ic < 32; ic++) {
            const float* wp = &w[((size_t)oc*1024 + icgBase + ic)*9];
            float wk[9];
#pragma unroll
            for (int t = 0; t < 9; t++) wk[t] = wp[t];
#pragma unroll
            for (int r = 0; r < 4; r++) {
                float xr[18];
#pragma unroll
                for (int t = 0; t < 18; t++) xr[t] = xs[ic][r][ws4*16 + t];
                if (r < 3) {
                    float w0 = wk[r*3], w1 = wk[r*3+1], w2 = wk[r*3+2];
#pragma unroll
                    for (int j = 0; j < 16; j++)
                        acc0[j] += xr[j]*w0 + xr[j+1]*w1 + xr[j+2]*w2;
                }
                if (r >= 1) {
                    float w0 = wk[(r-1)*3], w1 = wk[(r-1)*3+1], w2 = wk[(r-1)*3+2];
#pragma unroll
                    for (int j = 0; j < 16; j++)
                        acc1[j] += xr[j]*w0 + xr[j+1]*w1 + xr[j+2]*w2;
                }
            }
        }
        __syncthreads();
    }
    float bv = bias[oc];
#pragma unroll
    for (int j = 0; j < 16; j++) {
        g_y[(size_t)(b*512 + oc)*HW +  y0   *64 + ws4*16 + j] = acc0[j] + bv;
        g_y[(size_t)(b*512 + oc)*HW + (y0+1)*64 + ws4*16 + j] = acc1[j] + bv;
    }
}

// ---------------- K9: BatchNorm stats (per channel over B,H,W) ----------------
__global__ __launch_bounds__(256) void k9_bnstats()
{
    int c = blockIdx.x;
    float s = 0.f, ss = 0.f;
    for (int idx = threadIdx.x; idx < 32768; idx += 256) {
        int b = idx >> 12, p = idx & 4095;
        float v = g_y[(size_t)(b*512 + c)*HW + p];
        s += v; ss += v*v;
    }
    __shared__ float s1[8], s2[8];
    int tid = threadIdx.x;
#pragma unroll
    for (int o = 16; o; o >>= 1) {
        s  += __shfl_down_sync(0xffffffffu, s,  o);
        ss += __shfl_down_sync(0xffffffffu, ss, o);
    }
    if ((tid & 31) == 0) { s1[tid>>5] = s; s2[tid>>5] = ss; }
    __syncthreads();
    if (tid == 0) {
        float S = 0.f, SS = 0.f;
#pragma unroll
        for (int i = 0; i < 8; i++) { S += s1[i]; SS += s2[i]; }
        float m = S * (1.0f/32768.f);
        float var = SS * (1.0f/32768.f) - m*m;
        g_bn_mean[c] = m;
        g_bn_rstd[c] = rsqrtf(var + 1e-5f);
    }
}

// ---------------- K10: BN apply + SiLU -> out ----------------
__global__ __launch_bounds__(256) void k10_bn_silu(
    const float* __restrict__ gamma, const float* __restrict__ beta,
    float* __restrict__ out)
{
    int idx = blockIdx.x*256 + threadIdx.x;
    float v = g_y[idx];
    int ch = (idx >> 12) & 511;
    float yn = (v - g_bn_mean[ch]) * g_bn_rstd[ch] * gamma[ch] + beta[ch];
    out[idx] = yn * sigmoidf_(yn);
}

// ---------------- launch ----------------
extern "C" void kernel_launch(void* const* d_in, const int* in_sizes, int n_in,
                              void* d_out, int out_size)
{
    const float* x       = (const float*)d_in[0];
    const float* box_w1  = (const float*)d_in[1];
    const float* box_b1  = (const float*)d_in[2];
    const float* box_w2  = (const float*)d_in[3];
    const float* box_b2  = (const float*)d_in[4];
    const float* edge_w1 = (const float*)d_in[5];
    const float* edge_b1 = (const float*)d_in[6];
    const float* gn_g    = (const float*)d_in[7];
    const float* gn_b    = (const float*)d_in[8];
    const float* edge_w2 = (const float*)d_in[9];
    const float* edge_b2 = (const float*)d_in[10];
    const float* qkv_w   = (const float*)d_in[11];
    const float* qkv_b   = (const float*)d_in[12];
    const float* fus_w   = (const float*)d_in[13];
    const float* fus_b   = (const float*)d_in[14];
    const float* bn_g    = (const float*)d_in[15];
    const float* bn_b    = (const float*)d_in[16];
    float* out = (float*)d_out;

    k1_boxconv_gelu<<<dim3(64, 8), 256>>>(x, box_w1, box_b1);
    k2_box1x1_sig<<<128, 256>>>(box_w2, box_b2);
    k3_edgeconv<<<8192, 256>>>(edge_w1, edge_b1);
    k4_gnstats<<<64, 256>>>();
    k5_edge2<<<128, 256>>>(gn_g, gn_b, edge_w2, edge_b2);
    k6_qkv<<<dim3(64, 24, 8), 256>>>(x, qkv_w, qkv_b);
    k7a_scores<<<4096, 256>>>();
    k7b_softmax<<<4096, 64>>>();
    k7c_agg<<<4096, 256>>>();
    k8_fusion<<<dim3(8, 32, 8), 256>>>(x, fus_w, fus_b);
    k9_bnstats<<<512, 256>>>();
    k10_bn_silu<<<65536, 256>>>(bn_g, bn_b, out);
}